// round 10
// baseline (speedup 1.0000x reference)
#include <cuda_runtime.h>
#include <math.h>

// ---------------------------------------------------------------------------
// MenuLoss: fused loss over y_pred/y (512,7,16,64,2) + Chebyshev coeffs (447).
//
//   K1 menu_lut : Chebyshev LUT at the 223 integer ids (mask∘round_ste is the
//                 identity on integers <= 222 in fp32). Coeffs staged in smem
//                 so the serial 447-chain isn't gated on global-load latency.
//   K2 menu_main: 1 block per HALF batch row (grid=1024 for wave balance).
//                 Packed f32x2 Clenshaw for the true-id Chebyshev evals
//                 (1 packed FMA-slot / elem / coeff), LUT gather for the pred
//                 path, tanh penalties, block reduce -> per-unit partials.
//   K3 menu_fin : deterministic combine of 2 halves per batch, diff^2, mean.
// ---------------------------------------------------------------------------

#define N_COEFFS 447
#define INNER    7168          // 7*16*64
#define HALF     3584
#define TPB      256

__device__ float  g_lut[224];
__device__ float4 g_part[8192];   // (pen, pred, true, 0) per half-row unit

// ---- packed f32x2 helpers (sm_100+) ---------------------------------------
__device__ __forceinline__ unsigned long long pack2f(float lo, float hi) {
    unsigned long long r;
    asm("mov.b64 %0, {%1, %2};" : "=l"(r) : "f"(lo), "f"(hi));
    return r;
}
__device__ __forceinline__ void unpack2f(unsigned long long v, float& lo, float& hi) {
    asm("mov.b64 {%0, %1}, %2;" : "=f"(lo), "=f"(hi) : "l"(v));
}
__device__ __forceinline__ unsigned long long fma2(unsigned long long a,
                                                   unsigned long long b,
                                                   unsigned long long c) {
    unsigned long long d;
    asm("fma.rn.f32x2 %0, %1, %2, %3;" : "=l"(d) : "l"(a), "l"(b), "l"(c));
    return d;
}

__device__ __forceinline__ float warp_sum(float v) {
    #pragma unroll
    for (int o = 16; o > 0; o >>= 1) v += __shfl_xor_sync(0xffffffffu, v, o);
    return v;
}

// ---- K1: LUT at integer ids, mimicking the reference forward recurrence ----
__global__ void menu_lut(const float* __restrict__ coeffs) {
    __shared__ float sc[N_COEFFS];
    int tid = threadIdx.x;
    for (int i = tid; i < N_COEFFS; i += 256) sc[i] = coeffs[i];
    __syncthreads();
    int k = tid;
    if (k <= 222) {
        float xn  = (float)k / 111.0f - 1.0f;
        float Tm1 = 1.0f;
        float Tn  = xn;
        float acc = sc[0] + sc[1] * xn;
        float tx  = 2.0f * xn;
        #pragma unroll 5
        for (int i = 2; i < N_COEFFS; ++i) {
            float Tnew = tx * Tn - Tm1;
            acc += sc[i] * Tnew;
            Tm1 = Tn; Tn = Tnew;
        }
        g_lut[k] = acc;
    }
}

// ---- chunk worker: 2*NC elements, NC packed Clenshaw chains ----------------
template<int NC>
__device__ __forceinline__ void process_chunk(
    int tid, int jbase,
    const float2* __restrict__ p2, const float2* __restrict__ t2,
    const unsigned long long* __restrict__ sc, const float* __restrict__ slut,
    float& zacc, float& racc, float& pacc, float& tacc)
{
    float amt[2 * NC];
    unsigned long long twox[NC], b1[NC], b2[NC];

    #pragma unroll
    for (int i = 0; i < NC; ++i) {
        float xlo = 0.f, xhi = 0.f;
        #pragma unroll
        for (int h = 0; h < 2; ++h) {
            int s = 2 * i + h;
            int e = tid + (jbase + s) * TPB;
            float2 tv = t2[e];
            float2 pv = p2[e];
            float xn = tv.x / 111.0f - 1.0f;
            if (h == 0) xlo = xn; else xhi = xn;
            amt[s] = tv.y;
            // penalties on the pred side
            float a = tanhf(4.0f * pv.x);          // 1 - id_zero_mask
            float m = tanhf(4.0f * pv.y);          // amount_nonzero_mask
            zacc += (a + m) - 2.0f * a * m;        // case1 + case2
            racc += fmaxf(pv.x - 222.0f, 0.0f);    // relu(id - HIGHEST_ID)
            // pred calories via LUT (mask(round(id)) == round(id) exactly)
            int idx = (int)rintf(pv.x);
            idx = idx < 0 ? 0 : (idx > 222 ? 222 : idx);
            pacc = fmaf(slut[idx], pv.y, pacc);
        }
        twox[i] = pack2f(2.0f * xlo, 2.0f * xhi);
        b1[i] = 0ull;
        b2[i] = 0ull;
    }

    const unsigned long long NEG1 = pack2f(-1.0f, -1.0f);
    // Clenshaw: b_k = c_k + 2x*b_{k+1} - b_{k+2}, k = 446 .. 1
    #pragma unroll 2
    for (int k = N_COEFFS - 1; k >= 1; --k) {
        unsigned long long c2 = sc[k];
        #pragma unroll
        for (int i = 0; i < NC; ++i) {
            unsigned long long tmp = fma2(NEG1, b2[i], c2);      // c - b2
            unsigned long long bn  = fma2(twox[i], b1[i], tmp);  // + 2x*b1
            b2[i] = b1[i];
            b1[i] = bn;
        }
    }

    float c0, c0h;
    unpack2f(sc[0], c0, c0h);
    #pragma unroll
    for (int i = 0; i < NC; ++i) {
        float t0, t1, u0, u1, x0, x1;
        unpack2f(b1[i], t0, t1);
        unpack2f(b2[i], u0, u1);
        unpack2f(twox[i], x0, x1);
        float r0 = fmaf(0.5f * x0, t0, c0 - u0);  // result = c0 + x*b1 - b2
        float r1 = fmaf(0.5f * x1, t1, c0 - u1);
        tacc = fmaf(r0, amt[2 * i],     tacc);
        tacc = fmaf(r1, amt[2 * i + 1], tacc);
    }
}

// ---- K2: main, 1 block per half-row unit ----------------------------------
__global__ void __launch_bounds__(TPB, 4) menu_main(
    const float* __restrict__ y_pred,
    const float* __restrict__ y,
    const float* __restrict__ coeffs)
{
    __shared__ unsigned long long sc[N_COEFFS];  // coeff broadcast into both lanes
    __shared__ float slut[224];
    __shared__ float sw0[8], sw1[8], sw2[8];

    int tid = threadIdx.x;
    for (int i = tid; i < N_COEFFS; i += TPB) {
        float c = coeffs[i];
        sc[i] = pack2f(c, c);
    }
    if (tid < 223) slut[tid] = g_lut[tid];
    __syncthreads();

    int u = blockIdx.x;
    size_t base = (size_t)(u >> 1) * INNER + (size_t)(u & 1) * HALF;
    const float2* p2 = reinterpret_cast<const float2*>(y_pred) + base;
    const float2* t2 = reinterpret_cast<const float2*>(y)      + base;

    float z = 0.f, r = 0.f, p = 0.f, t = 0.f;
    // 3584 elems / 256 threads = 14 per thread: chunks {8, 6}
    process_chunk<4>(tid, 0, p2, t2, sc, slut, z, r, p, t);
    process_chunk<3>(tid, 8, p2, t2, sc, slut, z, r, p, t);

    float pen = z + r;
    pen = warp_sum(pen);
    p   = warp_sum(p);
    t   = warp_sum(t);

    int lane = tid & 31, w = tid >> 5;
    if (lane == 0) { sw0[w] = pen; sw1[w] = p; sw2[w] = t; }
    __syncthreads();
    if (w == 0) {
        float a = (lane < 8) ? sw0[lane] : 0.f;
        float q = (lane < 8) ? sw1[lane] : 0.f;
        float s = (lane < 8) ? sw2[lane] : 0.f;
        a = warp_sum(a); q = warp_sum(q); s = warp_sum(s);
        if (lane == 0) g_part[u] = make_float4(a, q, s, 0.f);
    }
}

// ---- K3: finalize ---------------------------------------------------------
__global__ void menu_fin(float* __restrict__ out, int B) {
    __shared__ float sred[16];
    int tid = threadIdx.x;
    float v = 0.f;
    for (int b = tid; b < B; b += 512) {
        float4 g0 = g_part[2 * b];
        float4 g1 = g_part[2 * b + 1];
        float pen  = g0.x + g1.x;
        float pred = (g0.y + g1.y) * (1.0f / 700.0f);
        float tru  = (g0.z + g1.z) * (1.0f / 700.0f);
        float d = tru - pred;
        v += pen + d * d;
    }
    v = warp_sum(v);
    int lane = tid & 31, w = tid >> 5;
    if (lane == 0) sred[w] = v;
    __syncthreads();
    if (w == 0) {
        float x = (lane < 16) ? sred[lane] : 0.f;
        x = warp_sum(x);
        if (lane == 0) out[0] = x / (float)B;
    }
}

// ---------------------------------------------------------------------------
extern "C" void kernel_launch(void* const* d_in, const int* in_sizes, int n_in,
                              void* d_out, int out_size) {
    const float* y_pred = (const float*)d_in[0];
    const float* y      = (const float*)d_in[1];
    const float* coeffs = (const float*)d_in[2];

    int B = in_sizes[0] / (2 * INNER);
    if (B < 1) B = 1;
    if (B > 4096) B = 4096;

    menu_lut<<<1, 256>>>(coeffs);
    menu_main<<<2 * B, TPB>>>(y_pred, y, coeffs);
    menu_fin<<<1, 512>>>((float*)d_out, B);
}

// round 11
// speedup vs baseline: 1.0067x; 1.0067x over previous
#include <cuda_runtime.h>
#include <math.h>

// ---------------------------------------------------------------------------
// MenuLoss: fused loss over y_pred/y (512,7,16,64,2) + Chebyshev coeffs (447).
//
//   K1 menu_lut : Chebyshev LUT at the 223 integer ids (mask∘round_ste is the
//                 identity on integers <= 222 in fp32). Coeffs staged in smem
//                 so the serial 447-chain isn't gated on global-load latency.
//   K2 menu_main: 1 block per HALF batch row (grid=1024 for wave balance).
//                 Packed f32x2 Clenshaw for the true-id Chebyshev evals
//                 (1 packed FMA-slot / elem / coeff), LUT gather for the pred
//                 path, tanh penalties, block reduce -> per-unit partials.
//   K3 menu_fin : deterministic combine of 2 halves per batch, diff^2, mean.
// ---------------------------------------------------------------------------

#define N_COEFFS 447
#define INNER    7168          // 7*16*64
#define HALF     3584
#define TPB      256

__device__ float  g_lut[224];
__device__ float4 g_part[8192];   // (pen, pred, true, 0) per half-row unit

// ---- packed f32x2 helpers (sm_100+) ---------------------------------------
__device__ __forceinline__ unsigned long long pack2f(float lo, float hi) {
    unsigned long long r;
    asm("mov.b64 %0, {%1, %2};" : "=l"(r) : "f"(lo), "f"(hi));
    return r;
}
__device__ __forceinline__ void unpack2f(unsigned long long v, float& lo, float& hi) {
    asm("mov.b64 {%0, %1}, %2;" : "=f"(lo), "=f"(hi) : "l"(v));
}
__device__ __forceinline__ unsigned long long fma2(unsigned long long a,
                                                   unsigned long long b,
                                                   unsigned long long c) {
    unsigned long long d;
    asm("fma.rn.f32x2 %0, %1, %2, %3;" : "=l"(d) : "l"(a), "l"(b), "l"(c));
    return d;
}

__device__ __forceinline__ float warp_sum(float v) {
    #pragma unroll
    for (int o = 16; o > 0; o >>= 1) v += __shfl_xor_sync(0xffffffffu, v, o);
    return v;
}

// ---- K1: LUT at integer ids, mimicking the reference forward recurrence ----
__global__ void menu_lut(const float* __restrict__ coeffs) {
    __shared__ float sc[N_COEFFS];
    int tid = threadIdx.x;
    for (int i = tid; i < N_COEFFS; i += 256) sc[i] = coeffs[i];
    __syncthreads();
    int k = tid;
    if (k <= 222) {
        float xn  = (float)k / 111.0f - 1.0f;
        float Tm1 = 1.0f;
        float Tn  = xn;
        float acc = sc[0] + sc[1] * xn;
        float tx  = 2.0f * xn;
        #pragma unroll 5
        for (int i = 2; i < N_COEFFS; ++i) {
            float Tnew = tx * Tn - Tm1;
            acc += sc[i] * Tnew;
            Tm1 = Tn; Tn = Tnew;
        }
        g_lut[k] = acc;
    }
}

// ---- chunk worker: 2*NC elements, NC packed Clenshaw chains ----------------
template<int NC>
__device__ __forceinline__ void process_chunk(
    int tid, int jbase,
    const float2* __restrict__ p2, const float2* __restrict__ t2,
    const unsigned long long* __restrict__ sc, const float* __restrict__ slut,
    float& zacc, float& racc, float& pacc, float& tacc)
{
    float amt[2 * NC];
    unsigned long long twox[NC], b1[NC], b2[NC];

    #pragma unroll
    for (int i = 0; i < NC; ++i) {
        float xlo = 0.f, xhi = 0.f;
        #pragma unroll
        for (int h = 0; h < 2; ++h) {
            int s = 2 * i + h;
            int e = tid + (jbase + s) * TPB;
            float2 tv = t2[e];
            float2 pv = p2[e];
            float xn = tv.x / 111.0f - 1.0f;
            if (h == 0) xlo = xn; else xhi = xn;
            amt[s] = tv.y;
            // penalties on the pred side
            float a = tanhf(4.0f * pv.x);          // 1 - id_zero_mask
            float m = tanhf(4.0f * pv.y);          // amount_nonzero_mask
            zacc += (a + m) - 2.0f * a * m;        // case1 + case2
            racc += fmaxf(pv.x - 222.0f, 0.0f);    // relu(id - HIGHEST_ID)
            // pred calories via LUT (mask(round(id)) == round(id) exactly)
            int idx = (int)rintf(pv.x);
            idx = idx < 0 ? 0 : (idx > 222 ? 222 : idx);
            pacc = fmaf(slut[idx], pv.y, pacc);
        }
        twox[i] = pack2f(2.0f * xlo, 2.0f * xhi);
        b1[i] = 0ull;
        b2[i] = 0ull;
    }

    const unsigned long long NEG1 = pack2f(-1.0f, -1.0f);
    // Clenshaw: b_k = c_k + 2x*b_{k+1} - b_{k+2}, k = 446 .. 1
    #pragma unroll 2
    for (int k = N_COEFFS - 1; k >= 1; --k) {
        unsigned long long c2 = sc[k];
        #pragma unroll
        for (int i = 0; i < NC; ++i) {
            unsigned long long tmp = fma2(NEG1, b2[i], c2);      // c - b2
            unsigned long long bn  = fma2(twox[i], b1[i], tmp);  // + 2x*b1
            b2[i] = b1[i];
            b1[i] = bn;
        }
    }

    float c0, c0h;
    unpack2f(sc[0], c0, c0h);
    #pragma unroll
    for (int i = 0; i < NC; ++i) {
        float t0, t1, u0, u1, x0, x1;
        unpack2f(b1[i], t0, t1);
        unpack2f(b2[i], u0, u1);
        unpack2f(twox[i], x0, x1);
        float r0 = fmaf(0.5f * x0, t0, c0 - u0);  // result = c0 + x*b1 - b2
        float r1 = fmaf(0.5f * x1, t1, c0 - u1);
        tacc = fmaf(r0, amt[2 * i],     tacc);
        tacc = fmaf(r1, amt[2 * i + 1], tacc);
    }
}

// ---- K2: main, 1 block per half-row unit ----------------------------------
__global__ void __launch_bounds__(TPB, 4) menu_main(
    const float* __restrict__ y_pred,
    const float* __restrict__ y,
    const float* __restrict__ coeffs)
{
    __shared__ unsigned long long sc[N_COEFFS];  // coeff broadcast into both lanes
    __shared__ float slut[224];
    __shared__ float sw0[8], sw1[8], sw2[8];

    int tid = threadIdx.x;
    for (int i = tid; i < N_COEFFS; i += TPB) {
        float c = coeffs[i];
        sc[i] = pack2f(c, c);
    }
    if (tid < 223) slut[tid] = g_lut[tid];
    __syncthreads();

    int u = blockIdx.x;
    size_t base = (size_t)(u >> 1) * INNER + (size_t)(u & 1) * HALF;
    const float2* p2 = reinterpret_cast<const float2*>(y_pred) + base;
    const float2* t2 = reinterpret_cast<const float2*>(y)      + base;

    float z = 0.f, r = 0.f, p = 0.f, t = 0.f;
    // 3584 elems / 256 threads = 14 per thread: chunks {8, 6}
    process_chunk<4>(tid, 0, p2, t2, sc, slut, z, r, p, t);
    process_chunk<3>(tid, 8, p2, t2, sc, slut, z, r, p, t);

    float pen = z + r;
    pen = warp_sum(pen);
    p   = warp_sum(p);
    t   = warp_sum(t);

    int lane = tid & 31, w = tid >> 5;
    if (lane == 0) { sw0[w] = pen; sw1[w] = p; sw2[w] = t; }
    __syncthreads();
    if (w == 0) {
        float a = (lane < 8) ? sw0[lane] : 0.f;
        float q = (lane < 8) ? sw1[lane] : 0.f;
        float s = (lane < 8) ? sw2[lane] : 0.f;
        a = warp_sum(a); q = warp_sum(q); s = warp_sum(s);
        if (lane == 0) g_part[u] = make_float4(a, q, s, 0.f);
    }
}

// ---- K3: finalize ---------------------------------------------------------
__global__ void menu_fin(float* __restrict__ out, int B) {
    __shared__ float sred[16];
    int tid = threadIdx.x;
    float v = 0.f;
    for (int b = tid; b < B; b += 512) {
        float4 g0 = g_part[2 * b];
        float4 g1 = g_part[2 * b + 1];
        float pen  = g0.x + g1.x;
        float pred = (g0.y + g1.y) * (1.0f / 700.0f);
        float tru  = (g0.z + g1.z) * (1.0f / 700.0f);
        float d = tru - pred;
        v += pen + d * d;
    }
    v = warp_sum(v);
    int lane = tid & 31, w = tid >> 5;
    if (lane == 0) sred[w] = v;
    __syncthreads();
    if (w == 0) {
        float x = (lane < 16) ? sred[lane] : 0.f;
        x = warp_sum(x);
        if (lane == 0) out[0] = x / (float)B;
    }
}

// ---------------------------------------------------------------------------
extern "C" void kernel_launch(void* const* d_in, const int* in_sizes, int n_in,
                              void* d_out, int out_size) {
    const float* y_pred = (const float*)d_in[0];
    const float* y      = (const float*)d_in[1];
    const float* coeffs = (const float*)d_in[2];

    int B = in_sizes[0] / (2 * INNER);
    if (B < 1) B = 1;
    if (B > 4096) B = 4096;

    menu_lut<<<1, 256>>>(coeffs);
    menu_main<<<2 * B, TPB>>>(y_pred, y, coeffs);
    menu_fin<<<1, 512>>>((float*)d_out, B);
}

// round 12
// speedup vs baseline: 1.0105x; 1.0038x over previous
#include <cuda_runtime.h>
#include <math.h>

// ---------------------------------------------------------------------------
// MenuLoss: fused loss over y_pred/y (512,7,16,64,2) + Chebyshev coeffs (447).
//
//   K1 menu_lut : Chebyshev LUT at the 223 integer ids (mask∘round_ste is the
//                 identity on integers <= 222 in fp32). Coeffs staged in smem
//                 so the serial 447-chain isn't gated on global-load latency.
//   K2 menu_main: 1 block per HALF batch row (grid=1024 for wave balance).
//                 Packed f32x2 Clenshaw for the true-id Chebyshev evals
//                 (1 packed FMA-slot / elem / coeff), LUT gather for the pred
//                 path, tanh penalties, block reduce -> per-unit partials.
//   K3 menu_fin : deterministic combine of 2 halves per batch, diff^2, mean.
// ---------------------------------------------------------------------------

#define N_COEFFS 447
#define INNER    7168          // 7*16*64
#define HALF     3584
#define TPB      256

__device__ float  g_lut[224];
__device__ float4 g_part[8192];   // (pen, pred, true, 0) per half-row unit

// ---- packed f32x2 helpers (sm_100+) ---------------------------------------
__device__ __forceinline__ unsigned long long pack2f(float lo, float hi) {
    unsigned long long r;
    asm("mov.b64 %0, {%1, %2};" : "=l"(r) : "f"(lo), "f"(hi));
    return r;
}
__device__ __forceinline__ void unpack2f(unsigned long long v, float& lo, float& hi) {
    asm("mov.b64 {%0, %1}, %2;" : "=f"(lo), "=f"(hi) : "l"(v));
}
__device__ __forceinline__ unsigned long long fma2(unsigned long long a,
                                                   unsigned long long b,
                                                   unsigned long long c) {
    unsigned long long d;
    asm("fma.rn.f32x2 %0, %1, %2, %3;" : "=l"(d) : "l"(a), "l"(b), "l"(c));
    return d;
}

__device__ __forceinline__ float warp_sum(float v) {
    #pragma unroll
    for (int o = 16; o > 0; o >>= 1) v += __shfl_xor_sync(0xffffffffu, v, o);
    return v;
}

// ---- K1: LUT at integer ids, mimicking the reference forward recurrence ----
__global__ void menu_lut(const float* __restrict__ coeffs) {
    __shared__ float sc[N_COEFFS];
    int tid = threadIdx.x;
    for (int i = tid; i < N_COEFFS; i += 256) sc[i] = coeffs[i];
    __syncthreads();
    int k = tid;
    if (k <= 222) {
        float xn  = (float)k / 111.0f - 1.0f;
        float Tm1 = 1.0f;
        float Tn  = xn;
        float acc = sc[0] + sc[1] * xn;
        float tx  = 2.0f * xn;
        #pragma unroll 5
        for (int i = 2; i < N_COEFFS; ++i) {
            float Tnew = tx * Tn - Tm1;
            acc += sc[i] * Tnew;
            Tm1 = Tn; Tn = Tnew;
        }
        g_lut[k] = acc;
    }
}

// ---- chunk worker: 2*NC elements, NC packed Clenshaw chains ----------------
template<int NC>
__device__ __forceinline__ void process_chunk(
    int tid, int jbase,
    const float2* __restrict__ p2, const float2* __restrict__ t2,
    const unsigned long long* __restrict__ sc, const float* __restrict__ slut,
    float& zacc, float& racc, float& pacc, float& tacc)
{
    float amt[2 * NC];
    unsigned long long twox[NC], b1[NC], b2[NC];

    #pragma unroll
    for (int i = 0; i < NC; ++i) {
        float xlo = 0.f, xhi = 0.f;
        #pragma unroll
        for (int h = 0; h < 2; ++h) {
            int s = 2 * i + h;
            int e = tid + (jbase + s) * TPB;
            float2 tv = t2[e];
            float2 pv = p2[e];
            float xn = tv.x / 111.0f - 1.0f;
            if (h == 0) xlo = xn; else xhi = xn;
            amt[s] = tv.y;
            // penalties on the pred side
            float a = tanhf(4.0f * pv.x);          // 1 - id_zero_mask
            float m = tanhf(4.0f * pv.y);          // amount_nonzero_mask
            zacc += (a + m) - 2.0f * a * m;        // case1 + case2
            racc += fmaxf(pv.x - 222.0f, 0.0f);    // relu(id - HIGHEST_ID)
            // pred calories via LUT (mask(round(id)) == round(id) exactly)
            int idx = (int)rintf(pv.x);
            idx = idx < 0 ? 0 : (idx > 222 ? 222 : idx);
            pacc = fmaf(slut[idx], pv.y, pacc);
        }
        twox[i] = pack2f(2.0f * xlo, 2.0f * xhi);
        b1[i] = 0ull;
        b2[i] = 0ull;
    }

    const unsigned long long NEG1 = pack2f(-1.0f, -1.0f);
    // Clenshaw: b_k = c_k + 2x*b_{k+1} - b_{k+2}, k = 446 .. 1
    #pragma unroll 2
    for (int k = N_COEFFS - 1; k >= 1; --k) {
        unsigned long long c2 = sc[k];
        #pragma unroll
        for (int i = 0; i < NC; ++i) {
            unsigned long long tmp = fma2(NEG1, b2[i], c2);      // c - b2
            unsigned long long bn  = fma2(twox[i], b1[i], tmp);  // + 2x*b1
            b2[i] = b1[i];
            b1[i] = bn;
        }
    }

    float c0, c0h;
    unpack2f(sc[0], c0, c0h);
    #pragma unroll
    for (int i = 0; i < NC; ++i) {
        float t0, t1, u0, u1, x0, x1;
        unpack2f(b1[i], t0, t1);
        unpack2f(b2[i], u0, u1);
        unpack2f(twox[i], x0, x1);
        float r0 = fmaf(0.5f * x0, t0, c0 - u0);  // result = c0 + x*b1 - b2
        float r1 = fmaf(0.5f * x1, t1, c0 - u1);
        tacc = fmaf(r0, amt[2 * i],     tacc);
        tacc = fmaf(r1, amt[2 * i + 1], tacc);
    }
}

// ---- K2: main, 1 block per half-row unit ----------------------------------
__global__ void __launch_bounds__(TPB, 4) menu_main(
    const float* __restrict__ y_pred,
    const float* __restrict__ y,
    const float* __restrict__ coeffs)
{
    __shared__ unsigned long long sc[N_COEFFS];  // coeff broadcast into both lanes
    __shared__ float slut[224];
    __shared__ float sw0[8], sw1[8], sw2[8];

    int tid = threadIdx.x;
    for (int i = tid; i < N_COEFFS; i += TPB) {
        float c = coeffs[i];
        sc[i] = pack2f(c, c);
    }
    if (tid < 223) slut[tid] = g_lut[tid];
    __syncthreads();

    int u = blockIdx.x;
    size_t base = (size_t)(u >> 1) * INNER + (size_t)(u & 1) * HALF;
    const float2* p2 = reinterpret_cast<const float2*>(y_pred) + base;
    const float2* t2 = reinterpret_cast<const float2*>(y)      + base;

    float z = 0.f, r = 0.f, p = 0.f, t = 0.f;
    // 3584 elems / 256 threads = 14 per thread: chunks {8, 6}
    process_chunk<4>(tid, 0, p2, t2, sc, slut, z, r, p, t);
    process_chunk<3>(tid, 8, p2, t2, sc, slut, z, r, p, t);

    float pen = z + r;
    pen = warp_sum(pen);
    p   = warp_sum(p);
    t   = warp_sum(t);

    int lane = tid & 31, w = tid >> 5;
    if (lane == 0) { sw0[w] = pen; sw1[w] = p; sw2[w] = t; }
    __syncthreads();
    if (w == 0) {
        float a = (lane < 8) ? sw0[lane] : 0.f;
        float q = (lane < 8) ? sw1[lane] : 0.f;
        float s = (lane < 8) ? sw2[lane] : 0.f;
        a = warp_sum(a); q = warp_sum(q); s = warp_sum(s);
        if (lane == 0) g_part[u] = make_float4(a, q, s, 0.f);
    }
}

// ---- K3: finalize ---------------------------------------------------------
__global__ void menu_fin(float* __restrict__ out, int B) {
    __shared__ float sred[16];
    int tid = threadIdx.x;
    float v = 0.f;
    for (int b = tid; b < B; b += 512) {
        float4 g0 = g_part[2 * b];
        float4 g1 = g_part[2 * b + 1];
        float pen  = g0.x + g1.x;
        float pred = (g0.y + g1.y) * (1.0f / 700.0f);
        float tru  = (g0.z + g1.z) * (1.0f / 700.0f);
        float d = tru - pred;
        v += pen + d * d;
    }
    v = warp_sum(v);
    int lane = tid & 31, w = tid >> 5;
    if (lane == 0) sred[w] = v;
    __syncthreads();
    if (w == 0) {
        float x = (lane < 16) ? sred[lane] : 0.f;
        x = warp_sum(x);
        if (lane == 0) out[0] = x / (float)B;
    }
}

// ---------------------------------------------------------------------------
extern "C" void kernel_launch(void* const* d_in, const int* in_sizes, int n_in,
                              void* d_out, int out_size) {
    const float* y_pred = (const float*)d_in[0];
    const float* y      = (const float*)d_in[1];
    const float* coeffs = (const float*)d_in[2];

    int B = in_sizes[0] / (2 * INNER);
    if (B < 1) B = 1;
    if (B > 4096) B = 4096;

    menu_lut<<<1, 256>>>(coeffs);
    menu_main<<<2 * B, TPB>>>(y_pred, y, coeffs);
    menu_fin<<<1, 512>>>((float*)d_out, B);
}